// round 11
// baseline (speedup 1.0000x reference)
#include <cuda_runtime.h>
#include <cstdint>

// ---------------- problem constants ----------------
#define NTOK   32768
#define OUT_FIBER  ((size_t)NTOK * 512)
#define OUT_CONN   (OUT_FIBER + (size_t)NTOK * 1024)
#define OUT_GEN    (OUT_CONN + (size_t)NTOK * 8)

// bf16 plane: 32 rows x 64B data, padded to 80B/row. hi plane at P, lo at P+PLANE.
#define ROWB   80
#define PLANE  2560
#define MATSM  (2 * PLANE)            // 5120 B per matrix
#define WPB    4                      // warps (matrices) per block

__device__ __forceinline__ void ldsm4(uint32_t a, uint32_t f[4]) {
    asm volatile("ldmatrix.sync.aligned.m8n8.x4.shared.b16 {%0,%1,%2,%3},[%4];"
                 : "=r"(f[0]), "=r"(f[1]), "=r"(f[2]), "=r"(f[3]) : "r"(a));
}
__device__ __forceinline__ void ldsm4t(uint32_t a, uint32_t f[4]) {
    asm volatile("ldmatrix.sync.aligned.m8n8.x4.trans.shared.b16 {%0,%1,%2,%3},[%4];"
                 : "=r"(f[0]), "=r"(f[1]), "=r"(f[2]), "=r"(f[3]) : "r"(a));
}
__device__ __forceinline__ void stsm4(uint32_t a, uint32_t r0, uint32_t r1,
                                      uint32_t r2, uint32_t r3) {
    asm volatile("stmatrix.sync.aligned.m8n8.x4.shared.b16 [%0],{%1,%2,%3,%4};"
                 :: "r"(a), "r"(r0), "r"(r1), "r"(r2), "r"(r3));
}
__device__ __forceinline__ void mmabf(float d[4], const uint32_t a[4],
                                      uint32_t b0, uint32_t b1) {
    asm volatile("mma.sync.aligned.m16n8k16.row.col.f32.bf16.bf16.f32 "
                 "{%0,%1,%2,%3},{%4,%5,%6,%7},{%8,%9},{%0,%1,%2,%3};"
                 : "+f"(d[0]), "+f"(d[1]), "+f"(d[2]), "+f"(d[3])
                 : "r"(a[0]), "r"(a[1]), "r"(a[2]), "r"(a[3]), "r"(b0), "r"(b1));
}

__device__ __forceinline__ uint32_t cvt2(float even, float odd) {
    uint32_t h; asm("cvt.rn.bf16x2.f32 %0,%1,%2;" : "=r"(h) : "f"(odd), "f"(even));
    return h;
}
__device__ __forceinline__ uint32_t lores(uint32_t h, float e, float o) {
    float he = __uint_as_float(h << 16);
    float ho = __uint_as_float(h & 0xffff0000u);
    return cvt2(e - he, o - ho);
}
__device__ __forceinline__ void sts4u(uint32_t a, uint32_t x, uint32_t y,
                                      uint32_t z, uint32_t w) {
    asm volatile("st.shared.v4.b32 [%0],{%1,%2,%3,%4};"
                 :: "r"(a), "r"(x), "r"(y), "r"(z), "r"(w));
}

__device__ __forceinline__ void packHL(const float (&D)[2][4][4],
                                       uint32_t (&H)[2][4][2], uint32_t (&L)[2][4][2]) {
    #pragma unroll
    for (int Mt = 0; Mt < 2; Mt++)
        #pragma unroll
        for (int nt = 0; nt < 4; nt++)
            #pragma unroll
            for (int rr = 0; rr < 2; rr++) {
                float e = D[Mt][nt][2 * rr], o = D[Mt][nt][2 * rr + 1];
                uint32_t h = cvt2(e, o);
                H[Mt][nt][rr] = h;
                L[Mt][nt][rr] = lores(h, e, o);
            }
}

__device__ __forceinline__ void zeroD(float (&D)[2][4][4]) {
    #pragma unroll
    for (int m = 0; m < 2; m++)
        #pragma unroll
        for (int n = 0; n < 4; n++)
            #pragma unroll
            for (int k = 0; k < 4; k++) D[m][n][k] = 0.0f;
}

// ---- Gram: D += M^T M, M in planes at P (3-product hi/lo) ----
__device__ __forceinline__ void gram(uint32_t P, float (&D)[2][4][4],
                                     int g1, int g2, int r7) {
    #pragma unroll
    for (int Kt = 0; Kt < 2; Kt++) {
        uint32_t ah[2][4], al[2][4], bh[2][4], bl[2][4];
        #pragma unroll
        for (int Mt = 0; Mt < 2; Mt++) {
            uint32_t off = (uint32_t)((Kt * 16 + g2 * 8 + r7) * ROWB + Mt * 32 + g1 * 16);
            ldsm4t(P + off, ah[Mt]);
            ldsm4t(P + PLANE + off, al[Mt]);
        }
        #pragma unroll
        for (int p = 0; p < 2; p++) {
            uint32_t off = (uint32_t)((Kt * 16 + g1 * 8 + r7) * ROWB + p * 32 + g2 * 16);
            ldsm4t(P + off, bh[p]);
            ldsm4t(P + PLANE + off, bl[p]);
        }
        #pragma unroll
        for (int Mt = 0; Mt < 2; Mt++)
            #pragma unroll
            for (int nt = 0; nt < 4; nt++) {
                const int p = nt >> 1, j = (nt & 1) * 2;
                mmabf(D[Mt][nt], ah[Mt], bh[p][j], bh[p][j + 1]);
                mmabf(D[Mt][nt], ah[Mt], bl[p][j], bl[p][j + 1]);
                mmabf(D[Mt][nt], al[Mt], bh[p][j], bh[p][j + 1]);
            }
    }
}

// ---- rmul: D += M * T, M in planes at P, T symmetric in reg packs ----
__device__ __forceinline__ void rmul(uint32_t P,
                                     const uint32_t (&TH)[2][4][2],
                                     const uint32_t (&TL)[2][4][2],
                                     float (&D)[2][4][4], int g1, int g2, int r7) {
    #pragma unroll
    for (int Kt = 0; Kt < 2; Kt++) {
        uint32_t ah[2][4], al[2][4];
        #pragma unroll
        for (int Mt = 0; Mt < 2; Mt++) {
            uint32_t off = (uint32_t)((Mt * 16 + g1 * 8 + r7) * ROWB + Kt * 32 + g2 * 16);
            ldsm4(P + off, ah[Mt]);
            ldsm4(P + PLANE + off, al[Mt]);
        }
        #pragma unroll
        for (int Mt = 0; Mt < 2; Mt++)
            #pragma unroll
            for (int nt = 0; nt < 4; nt++) {
                uint32_t b0h = TH[nt >> 1][2 * Kt    ][nt & 1];
                uint32_t b1h = TH[nt >> 1][2 * Kt + 1][nt & 1];
                uint32_t b0l = TL[nt >> 1][2 * Kt    ][nt & 1];
                uint32_t b1l = TL[nt >> 1][2 * Kt + 1][nt & 1];
                mmabf(D[Mt][nt], ah[Mt], b0h, b1h);
                mmabf(D[Mt][nt], ah[Mt], b0l, b1l);
                mmabf(D[Mt][nt], al[Mt], b0h, b1h);
            }
    }
}

// ---- sqsym: D += G * G, G symmetric, entirely from reg packs ----
__device__ __forceinline__ void sqsym(const uint32_t (&GH)[2][4][2],
                                      const uint32_t (&GL)[2][4][2],
                                      float (&D)[2][4][4]) {
    #pragma unroll
    for (int Kt = 0; Kt < 2; Kt++)
        #pragma unroll
        for (int Mt = 0; Mt < 2; Mt++) {
            uint32_t aH[4] = {GH[Mt][2*Kt][0], GH[Mt][2*Kt][1],
                              GH[Mt][2*Kt+1][0], GH[Mt][2*Kt+1][1]};
            uint32_t aL[4] = {GL[Mt][2*Kt][0], GL[Mt][2*Kt][1],
                              GL[Mt][2*Kt+1][0], GL[Mt][2*Kt+1][1]};
            #pragma unroll
            for (int nt = 0; nt < 4; nt++) {
                uint32_t b0h = GH[nt >> 1][2 * Kt    ][nt & 1];
                uint32_t b1h = GH[nt >> 1][2 * Kt + 1][nt & 1];
                uint32_t b0l = GL[nt >> 1][2 * Kt    ][nt & 1];
                uint32_t b1l = GL[nt >> 1][2 * Kt + 1][nt & 1];
                mmabf(D[Mt][nt], aH, b0h, b1h);
                mmabf(D[Mt][nt], aH, b0l, b1l);
                mmabf(D[Mt][nt], aL, b0h, b1h);
            }
        }
}

__global__ __launch_bounds__(32 * WPB) void fiber_bundle_kernel(
    const int*   __restrict__ tokens,
    const float* __restrict__ base_w,
    const float* __restrict__ fiber_w,
    const float* __restrict__ conn_w,
    const float* __restrict__ gen,
    float*       __restrict__ out)
{
    __shared__ __align__(128) char smraw[WPB * MATSM];
    const int wid  = threadIdx.x >> 5;
    const int lane = threadIdx.x & 31;
    const uint32_t P1h = (uint32_t)__cvta_generic_to_shared(smraw) + wid * MATSM;

    const int g  = lane >> 3;
    const int g1 = g & 1, g2 = g >> 1;
    const int r7 = lane & 7;
    const int rw = lane >> 2;
    const int cp = (lane & 3) * 2;

    const int tokIdx = blockIdx.x * WPB + wid;
    const int tok    = tokens[tokIdx];

    // ---- side-copy loads issued early ----
    float4 breg[4];
    {
        const float4* bsrc = (const float4*)(base_w + (size_t)tok * 512);
        #pragma unroll
        for (int j = 0; j < 4; j++) breg[j] = bsrc[lane + 32 * j];
    }
    float cv = 0.0f;
    if (lane < 8) cv = conn_w[(size_t)tok * 8 + lane];
    float4 gv;
    const bool doGen = blockIdx.x < 16;    // 16 blocks x 128 threads = 2048 float4
    if (doGen) gv = ((const float4*)gen)[blockIdx.x * 128 + threadIdx.x];

    // ---- load X (8 row-contiguous floats per lane-iter), split to hi/lo planes ----
    {
        const float4* fsrc = (const float4*)(fiber_w + (size_t)tok * 1024);
        #pragma unroll
        for (int i = 0; i < 4; i++) {
            int p = i * 32 + lane;
            float4 v0 = fsrc[2 * p];
            float4 v1 = fsrc[2 * p + 1];
            int row = p >> 2, c8 = (p & 3) * 8;
            uint32_t a = P1h + (uint32_t)(row * ROWB + c8 * 2);
            uint32_t h0 = cvt2(v0.x, v0.y), h1 = cvt2(v0.z, v0.w);
            uint32_t h2 = cvt2(v1.x, v1.y), h3 = cvt2(v1.z, v1.w);
            sts4u(a, h0, h1, h2, h3);
            sts4u(a + PLANE, lores(h0, v0.x, v0.y), lores(h1, v0.z, v0.w),
                             lores(h2, v1.x, v1.y), lores(h3, v1.z, v1.w));
        }
    }

    // ---- retire side copies ----
    {
        float4* bdst = (float4*)(out + (size_t)tokIdx * 512);
        #pragma unroll
        for (int j = 0; j < 4; j++) bdst[lane + 32 * j] = breg[j];
    }
    if (lane < 8) out[OUT_CONN + (size_t)tokIdx * 8 + lane] = cv;
    if (doGen) ((float4*)(out + OUT_GEN))[blockIdx.x * 128 + threadIdx.x] = gv;

    __syncwarp();

    float D[2][4][4];
    uint32_t H[2][4][2], L[2][4][2];

    // ===== (1) G = X^T X =====
    zeroD(D);
    gram(P1h, D, g1, g2, r7);

    // ===== (2) T = 0.375*(G*G + 5I - (10/3)G)  (regs only) =====
    packHL(D, H, L);
    #pragma unroll
    for (int Mt = 0; Mt < 2; Mt++)
        #pragma unroll
        for (int nt = 0; nt < 4; nt++) {
            const int c0 = nt * 8 + cp;
            const int r0 = Mt * 16 + rw, r1 = r0 + 8;
            D[Mt][nt][0] = fmaf(D[Mt][nt][0], -3.33333333f, (r0 == c0)     ? 5.0f : 0.0f);
            D[Mt][nt][1] = fmaf(D[Mt][nt][1], -3.33333333f, (r0 == c0 + 1) ? 5.0f : 0.0f);
            D[Mt][nt][2] = fmaf(D[Mt][nt][2], -3.33333333f, (r1 == c0)     ? 5.0f : 0.0f);
            D[Mt][nt][3] = fmaf(D[Mt][nt][3], -3.33333333f, (r1 == c0 + 1) ? 5.0f : 0.0f);
        }
    sqsym(H, L, D);
    #pragma unroll
    for (int Mt = 0; Mt < 2; Mt++)
        #pragma unroll
        for (int nt = 0; nt < 4; nt++)
            #pragma unroll
            for (int k = 0; k < 4; k++) D[Mt][nt][k] *= 0.375f;
    packHL(D, H, L);                       // T packs

    // ===== (3) X1 = X * T =====
    zeroD(D);
    rmul(P1h, H, L, D, g1, g2, r7);
    packHL(D, H, L);                       // X1 packs
    __syncwarp();
    #pragma unroll
    for (int r = 0; r < 4; r++) {
        uint32_t a = P1h + (uint32_t)((8 * r + r7) * ROWB + g * 16);
        stsm4(a,         H[r >> 1][0][r & 1], H[r >> 1][1][r & 1],
                         H[r >> 1][2][r & 1], H[r >> 1][3][r & 1]);
        stsm4(a + PLANE, L[r >> 1][0][r & 1], L[r >> 1][1][r & 1],
                         L[r >> 1][2][r & 1], L[r >> 1][3][r & 1]);
    }
    __syncwarp();

    // ===== (4) G2 = X1^T X1 ; T2 = 1.5I - 0.5 G2 =====
    zeroD(D);
    gram(P1h, D, g1, g2, r7);
    #pragma unroll
    for (int Mt = 0; Mt < 2; Mt++)
        #pragma unroll
        for (int nt = 0; nt < 4; nt++) {
            const int c0 = nt * 8 + cp;
            const int r0 = Mt * 16 + rw, r1 = r0 + 8;
            D[Mt][nt][0] = fmaf(D[Mt][nt][0], -0.5f, (r0 == c0)     ? 1.5f : 0.0f);
            D[Mt][nt][1] = fmaf(D[Mt][nt][1], -0.5f, (r0 == c0 + 1) ? 1.5f : 0.0f);
            D[Mt][nt][2] = fmaf(D[Mt][nt][2], -0.5f, (r1 == c0)     ? 1.5f : 0.0f);
            D[Mt][nt][3] = fmaf(D[Mt][nt][3], -0.5f, (r1 == c0 + 1) ? 1.5f : 0.0f);
        }
    packHL(D, H, L);                       // T2 packs

    // ===== (5) Xf = X1 * T2 -> gmem =====
    zeroD(D);
    rmul(P1h, H, L, D, g1, g2, r7);

    {
        float* fdst = out + OUT_FIBER + (size_t)tokIdx * 1024;
        #pragma unroll
        for (int Mt = 0; Mt < 2; Mt++)
            #pragma unroll
            for (int nt = 0; nt < 4; nt++) {
                const int c0 = nt * 8 + cp;
                const int r0 = Mt * 16 + rw;
                *(float2*)(fdst + r0 * 32 + c0)       = make_float2(D[Mt][nt][0], D[Mt][nt][1]);
                *(float2*)(fdst + (r0 + 8) * 32 + c0) = make_float2(D[Mt][nt][2], D[Mt][nt][3]);
            }
    }
}

extern "C" void kernel_launch(void* const* d_in, const int* in_sizes, int n_in,
                              void* d_out, int out_size)
{
    const int*   tokens  = (const int*)  d_in[0];
    const float* base_w  = (const float*)d_in[1];
    const float* fiber_w = (const float*)d_in[2];
    const float* conn_w  = (const float*)d_in[3];
    const float* gen     = (const float*)d_in[4];
    float* out = (float*)d_out;

    static bool configured = false;
    if (!configured) {
        cudaFuncSetAttribute(fiber_bundle_kernel,
                             cudaFuncAttributePreferredSharedMemoryCarveout, 100);
        configured = true;
    }

    dim3 grid(NTOK / WPB);   // 8192 blocks, 4 warps (matrices) each
    dim3 block(32 * WPB);
    fiber_bundle_kernel<<<grid, block>>>(tokens, base_w, fiber_w, conn_w, gen, out);
}

// round 12
// speedup vs baseline: 1.0330x; 1.0330x over previous
#include <cuda_runtime.h>
#include <cstdint>

// ---------------- problem constants ----------------
#define NTOK   32768
#define OUT_FIBER  ((size_t)NTOK * 512)
#define OUT_CONN   (OUT_FIBER + (size_t)NTOK * 1024)
#define OUT_GEN    (OUT_CONN + (size_t)NTOK * 8)

// bf16 plane: 32 rows x 64B data, padded to 80B/row. hi plane at P, lo at P+PLANE.
#define ROWB   80
#define PLANE  2560

__device__ __forceinline__ void ldsm4(uint32_t a, uint32_t f[4]) {
    asm volatile("ldmatrix.sync.aligned.m8n8.x4.shared.b16 {%0,%1,%2,%3},[%4];"
                 : "=r"(f[0]), "=r"(f[1]), "=r"(f[2]), "=r"(f[3]) : "r"(a));
}
__device__ __forceinline__ void ldsm4t(uint32_t a, uint32_t f[4]) {
    asm volatile("ldmatrix.sync.aligned.m8n8.x4.trans.shared.b16 {%0,%1,%2,%3},[%4];"
                 : "=r"(f[0]), "=r"(f[1]), "=r"(f[2]), "=r"(f[3]) : "r"(a));
}
__device__ __forceinline__ void stsm4(uint32_t a, uint32_t r0, uint32_t r1,
                                      uint32_t r2, uint32_t r3) {
    asm volatile("stmatrix.sync.aligned.m8n8.x4.shared.b16 [%0],{%1,%2,%3,%4};"
                 :: "r"(a), "r"(r0), "r"(r1), "r"(r2), "r"(r3));
}
__device__ __forceinline__ void mmabf(float d[4], const uint32_t a[4],
                                      uint32_t b0, uint32_t b1) {
    asm volatile("mma.sync.aligned.m16n8k16.row.col.f32.bf16.bf16.f32 "
                 "{%0,%1,%2,%3},{%4,%5,%6,%7},{%8,%9},{%0,%1,%2,%3};"
                 : "+f"(d[0]), "+f"(d[1]), "+f"(d[2]), "+f"(d[3])
                 : "r"(a[0]), "r"(a[1]), "r"(a[2]), "r"(a[3]), "r"(b0), "r"(b1));
}

__device__ __forceinline__ uint32_t cvt2(float even, float odd) {
    uint32_t h; asm("cvt.rn.bf16x2.f32 %0,%1,%2;" : "=r"(h) : "f"(odd), "f"(even));
    return h;
}
__device__ __forceinline__ uint32_t lores(uint32_t h, float e, float o) {
    float he = __uint_as_float(h << 16);
    float ho = __uint_as_float(h & 0xffff0000u);
    return cvt2(e - he, o - ho);
}
__device__ __forceinline__ void sts4u(uint32_t a, uint32_t x, uint32_t y,
                                      uint32_t z, uint32_t w) {
    asm volatile("st.shared.v4.b32 [%0],{%1,%2,%3,%4};"
                 :: "r"(a), "r"(x), "r"(y), "r"(z), "r"(w));
}

__device__ __forceinline__ void packHL(const float (&D)[2][4][4],
                                       uint32_t (&H)[2][4][2], uint32_t (&L)[2][4][2]) {
    #pragma unroll
    for (int Mt = 0; Mt < 2; Mt++)
        #pragma unroll
        for (int nt = 0; nt < 4; nt++)
            #pragma unroll
            for (int rr = 0; rr < 2; rr++) {
                float e = D[Mt][nt][2 * rr], o = D[Mt][nt][2 * rr + 1];
                uint32_t h = cvt2(e, o);
                H[Mt][nt][rr] = h;
                L[Mt][nt][rr] = lores(h, e, o);
            }
}

__device__ __forceinline__ void zeroD(float (&D)[2][4][4]) {
    #pragma unroll
    for (int m = 0; m < 2; m++)
        #pragma unroll
        for (int n = 0; n < 4; n++)
            #pragma unroll
            for (int k = 0; k < 4; k++) D[m][n][k] = 0.0f;
}

// ---- Gram: D += M^T M, M in planes at P (3-product hi/lo) ----
__device__ __forceinline__ void gram(uint32_t P, float (&D)[2][4][4],
                                     int g1, int g2, int r7) {
    #pragma unroll
    for (int Kt = 0; Kt < 2; Kt++) {
        uint32_t ah[2][4], al[2][4], bh[2][4], bl[2][4];
        #pragma unroll
        for (int Mt = 0; Mt < 2; Mt++) {
            uint32_t off = (uint32_t)((Kt * 16 + g2 * 8 + r7) * ROWB + Mt * 32 + g1 * 16);
            ldsm4t(P + off, ah[Mt]);
            ldsm4t(P + PLANE + off, al[Mt]);
        }
        #pragma unroll
        for (int p = 0; p < 2; p++) {
            uint32_t off = (uint32_t)((Kt * 16 + g1 * 8 + r7) * ROWB + p * 32 + g2 * 16);
            ldsm4t(P + off, bh[p]);
            ldsm4t(P + PLANE + off, bl[p]);
        }
        #pragma unroll
        for (int Mt = 0; Mt < 2; Mt++)
            #pragma unroll
            for (int nt = 0; nt < 4; nt++) {
                const int p = nt >> 1, j = (nt & 1) * 2;
                mmabf(D[Mt][nt], ah[Mt], bh[p][j], bh[p][j + 1]);
                mmabf(D[Mt][nt], ah[Mt], bl[p][j], bl[p][j + 1]);
                mmabf(D[Mt][nt], al[Mt], bh[p][j], bh[p][j + 1]);
            }
    }
}

// ---- rmul: D += M * T, M in planes at P, T symmetric in reg packs ----
__device__ __forceinline__ void rmul(uint32_t P,
                                     const uint32_t (&TH)[2][4][2],
                                     const uint32_t (&TL)[2][4][2],
                                     float (&D)[2][4][4], int g1, int g2, int r7) {
    #pragma unroll
    for (int Kt = 0; Kt < 2; Kt++) {
        uint32_t ah[2][4], al[2][4];
        #pragma unroll
        for (int Mt = 0; Mt < 2; Mt++) {
            uint32_t off = (uint32_t)((Mt * 16 + g1 * 8 + r7) * ROWB + Kt * 32 + g2 * 16);
            ldsm4(P + off, ah[Mt]);
            ldsm4(P + PLANE + off, al[Mt]);
        }
        #pragma unroll
        for (int Mt = 0; Mt < 2; Mt++)
            #pragma unroll
            for (int nt = 0; nt < 4; nt++) {
                uint32_t b0h = TH[nt >> 1][2 * Kt    ][nt & 1];
                uint32_t b1h = TH[nt >> 1][2 * Kt + 1][nt & 1];
                uint32_t b0l = TL[nt >> 1][2 * Kt    ][nt & 1];
                uint32_t b1l = TL[nt >> 1][2 * Kt + 1][nt & 1];
                mmabf(D[Mt][nt], ah[Mt], b0h, b1h);
                mmabf(D[Mt][nt], ah[Mt], b0l, b1l);
                mmabf(D[Mt][nt], al[Mt], b0h, b1h);
            }
    }
}

// ---- rmulE: D += Mhi * E, E (tiny, symmetric) single bf16 plane in regs ----
__device__ __forceinline__ void rmulE(uint32_t P, const uint32_t (&EH)[2][4][2],
                                      float (&D)[2][4][4], int g1, int g2, int r7) {
    #pragma unroll
    for (int Kt = 0; Kt < 2; Kt++) {
        uint32_t ah[2][4];
        #pragma unroll
        for (int Mt = 0; Mt < 2; Mt++) {
            uint32_t off = (uint32_t)((Mt * 16 + g1 * 8 + r7) * ROWB + Kt * 32 + g2 * 16);
            ldsm4(P + off, ah[Mt]);
        }
        #pragma unroll
        for (int Mt = 0; Mt < 2; Mt++)
            #pragma unroll
            for (int nt = 0; nt < 4; nt++)
                mmabf(D[Mt][nt], ah[Mt],
                      EH[nt >> 1][2 * Kt    ][nt & 1],
                      EH[nt >> 1][2 * Kt + 1][nt & 1]);
    }
}

// ---- sqsym: D += G * G, G symmetric, entirely from reg packs ----
__device__ __forceinline__ void sqsym(const uint32_t (&GH)[2][4][2],
                                      const uint32_t (&GL)[2][4][2],
                                      float (&D)[2][4][4]) {
    #pragma unroll
    for (int Kt = 0; Kt < 2; Kt++)
        #pragma unroll
        for (int Mt = 0; Mt < 2; Mt++) {
            uint32_t aH[4] = {GH[Mt][2*Kt][0], GH[Mt][2*Kt][1],
                              GH[Mt][2*Kt+1][0], GH[Mt][2*Kt+1][1]};
            uint32_t aL[4] = {GL[Mt][2*Kt][0], GL[Mt][2*Kt][1],
                              GL[Mt][2*Kt+1][0], GL[Mt][2*Kt+1][1]};
            #pragma unroll
            for (int nt = 0; nt < 4; nt++) {
                uint32_t b0h = GH[nt >> 1][2 * Kt    ][nt & 1];
                uint32_t b1h = GH[nt >> 1][2 * Kt + 1][nt & 1];
                uint32_t b0l = GL[nt >> 1][2 * Kt    ][nt & 1];
                uint32_t b1l = GL[nt >> 1][2 * Kt + 1][nt & 1];
                mmabf(D[Mt][nt], aH, b0h, b1h);
                mmabf(D[Mt][nt], aH, b0l, b1l);
                mmabf(D[Mt][nt], aL, b0h, b1h);
            }
        }
}

__global__ __launch_bounds__(32) void fiber_bundle_kernel(
    const int*   __restrict__ tokens,
    const float* __restrict__ base_w,
    const float* __restrict__ fiber_w,
    const float* __restrict__ conn_w,
    const float* __restrict__ gen,
    float*       __restrict__ out)
{
    __shared__ __align__(128) char smraw[2 * PLANE];
    const uint32_t P1h = (uint32_t)__cvta_generic_to_shared(smraw);   // X -> X1

    const int lane = threadIdx.x;
    const int g  = lane >> 3;
    const int g1 = g & 1, g2 = g >> 1;
    const int r7 = lane & 7;
    const int rw = lane >> 2;
    const int cp = (lane & 3) * 2;

    const int tokIdx = blockIdx.x;
    const int tok    = tokens[tokIdx];

    // ---- side-copy loads issued early ----
    float4 breg[4];
    {
        const float4* bsrc = (const float4*)(base_w + (size_t)tok * 512);
        #pragma unroll
        for (int j = 0; j < 4; j++) breg[j] = bsrc[lane + 32 * j];
    }
    float cv = 0.0f;
    if (lane < 8) cv = conn_w[(size_t)tok * 8 + lane];
    float4 gv;
    const bool doGen = blockIdx.x < 64;
    if (doGen) gv = ((const float4*)gen)[blockIdx.x * 32 + lane];

    // ---- load X (8 row-contiguous floats per lane-iter), split to hi/lo planes ----
    {
        const float4* fsrc = (const float4*)(fiber_w + (size_t)tok * 1024);
        #pragma unroll
        for (int i = 0; i < 4; i++) {
            int p = i * 32 + lane;
            float4 v0 = fsrc[2 * p];
            float4 v1 = fsrc[2 * p + 1];
            int row = p >> 2, c8 = (p & 3) * 8;
            uint32_t a = P1h + (uint32_t)(row * ROWB + c8 * 2);
            uint32_t h0 = cvt2(v0.x, v0.y), h1 = cvt2(v0.z, v0.w);
            uint32_t h2 = cvt2(v1.x, v1.y), h3 = cvt2(v1.z, v1.w);
            sts4u(a, h0, h1, h2, h3);
            sts4u(a + PLANE, lores(h0, v0.x, v0.y), lores(h1, v0.z, v0.w),
                             lores(h2, v1.x, v1.y), lores(h3, v1.z, v1.w));
        }
    }

    // ---- retire side copies ----
    {
        float4* bdst = (float4*)(out + (size_t)tokIdx * 512);
        #pragma unroll
        for (int j = 0; j < 4; j++) bdst[lane + 32 * j] = breg[j];
    }
    if (lane < 8) out[OUT_CONN + (size_t)tokIdx * 8 + lane] = cv;
    if (doGen) ((float4*)(out + OUT_GEN))[blockIdx.x * 32 + lane] = gv;

    __syncwarp();

    float D[2][4][4];
    uint32_t H[2][4][2], L[2][4][2];

    // ===== (1) G = X^T X =====
    zeroD(D);
    gram(P1h, D, g1, g2, r7);

    // ===== (2) T = 0.375*(G*G + 5I - (10/3)G)  (regs only) =====
    packHL(D, H, L);                       // G packs
    #pragma unroll
    for (int Mt = 0; Mt < 2; Mt++)
        #pragma unroll
        for (int nt = 0; nt < 4; nt++) {
            const int c0 = nt * 8 + cp;
            const int r0 = Mt * 16 + rw, r1 = r0 + 8;
            D[Mt][nt][0] = fmaf(D[Mt][nt][0], -3.33333333f, (r0 == c0)     ? 5.0f : 0.0f);
            D[Mt][nt][1] = fmaf(D[Mt][nt][1], -3.33333333f, (r0 == c0 + 1) ? 5.0f : 0.0f);
            D[Mt][nt][2] = fmaf(D[Mt][nt][2], -3.33333333f, (r1 == c0)     ? 5.0f : 0.0f);
            D[Mt][nt][3] = fmaf(D[Mt][nt][3], -3.33333333f, (r1 == c0 + 1) ? 5.0f : 0.0f);
        }
    sqsym(H, L, D);
    #pragma unroll
    for (int Mt = 0; Mt < 2; Mt++)
        #pragma unroll
        for (int nt = 0; nt < 4; nt++)
            #pragma unroll
            for (int k = 0; k < 4; k++) D[Mt][nt][k] *= 0.375f;
    packHL(D, H, L);                       // T packs

    // ===== (3) X1 = X * T  (D holds X1 in fp32 afterwards) =====
    zeroD(D);
    rmul(P1h, H, L, D, g1, g2, r7);
    packHL(D, H, L);                       // X1 packs
    __syncwarp();
    #pragma unroll
    for (int r = 0; r < 4; r++) {          // X1 -> planes via stmatrix
        uint32_t a = P1h + (uint32_t)((8 * r + r7) * ROWB + g * 16);
        stsm4(a,         H[r >> 1][0][r & 1], H[r >> 1][1][r & 1],
                         H[r >> 1][2][r & 1], H[r >> 1][3][r & 1]);
        stsm4(a + PLANE, L[r >> 1][0][r & 1], L[r >> 1][1][r & 1],
                         L[r >> 1][2][r & 1], L[r >> 1][3][r & 1]);
    }
    __syncwarp();

    // ===== (4) G2 = X1^T X1 (fresh accum C; D keeps X1 fp32) =====
    float C[2][4][4];
    zeroD(C);
    gram(P1h, C, g1, g2, r7);

    // E = 0.5*(I - G2)  (tiny, symmetric) -> single bf16 plane in regs
    uint32_t EH[2][4][2];
    #pragma unroll
    for (int Mt = 0; Mt < 2; Mt++)
        #pragma unroll
        for (int nt = 0; nt < 4; nt++) {
            const int c0 = nt * 8 + cp;
            const int r0 = Mt * 16 + rw, r1 = r0 + 8;
            float e0 = 0.5f * (((r0 == c0)     ? 1.0f : 0.0f) - C[Mt][nt][0]);
            float e1 = 0.5f * (((r0 == c0 + 1) ? 1.0f : 0.0f) - C[Mt][nt][1]);
            float e2 = 0.5f * (((r1 == c0)     ? 1.0f : 0.0f) - C[Mt][nt][2]);
            float e3 = 0.5f * (((r1 == c0 + 1) ? 1.0f : 0.0f) - C[Mt][nt][3]);
            EH[Mt][nt][0] = cvt2(e0, e1);
            EH[Mt][nt][1] = cvt2(e2, e3);
        }

    // ===== (5) Xf = X1 + X1h * E  (accumulate into D, which holds X1 fp32) =====
    rmulE(P1h, EH, D, g1, g2, r7);

    {
        float* fdst = out + OUT_FIBER + (size_t)tokIdx * 1024;
        #pragma unroll
        for (int Mt = 0; Mt < 2; Mt++)
            #pragma unroll
            for (int nt = 0; nt < 4; nt++) {
                const int c0 = nt * 8 + cp;
                const int r0 = Mt * 16 + rw;
                *(float2*)(fdst + r0 * 32 + c0)       = make_float2(D[Mt][nt][0], D[Mt][nt][1]);
                *(float2*)(fdst + (r0 + 8) * 32 + c0) = make_float2(D[Mt][nt][2], D[Mt][nt][3]);
            }
    }
}

extern "C" void kernel_launch(void* const* d_in, const int* in_sizes, int n_in,
                              void* d_out, int out_size)
{
    const int*   tokens  = (const int*)  d_in[0];
    const float* base_w  = (const float*)d_in[1];
    const float* fiber_w = (const float*)d_in[2];
    const float* conn_w  = (const float*)d_in[3];
    const float* gen     = (const float*)d_in[4];
    float* out = (float*)d_out;

    static bool configured = false;
    if (!configured) {
        cudaFuncSetAttribute(fiber_bundle_kernel,
                             cudaFuncAttributePreferredSharedMemoryCarveout, 100);
        configured = true;
    }

    dim3 grid(NTOK);       // 32768 one-warp blocks, 1 matrix each
    dim3 block(32);
    fiber_bundle_kernel<<<grid, block>>>(tokens, base_w, fiber_w, conn_w, gen, out);
}

// round 13
// speedup vs baseline: 1.1527x; 1.1159x over previous
#include <cuda_runtime.h>
#include <cstdint>

// ---------------- problem constants ----------------
#define NTOK   32768
#define OUT_FIBER  ((size_t)NTOK * 512)
#define OUT_CONN   (OUT_FIBER + (size_t)NTOK * 1024)
#define OUT_GEN    (OUT_CONN + (size_t)NTOK * 8)

__device__ __forceinline__ void mmabf(float d[4], const uint32_t a[4],
                                      uint32_t b0, uint32_t b1) {
    asm volatile("mma.sync.aligned.m16n8k16.row.col.f32.bf16.bf16.f32 "
                 "{%0,%1,%2,%3},{%4,%5,%6,%7},{%8,%9},{%0,%1,%2,%3};"
                 : "+f"(d[0]), "+f"(d[1]), "+f"(d[2]), "+f"(d[3])
                 : "r"(a[0]), "r"(a[1]), "r"(a[2]), "r"(a[3]), "r"(b0), "r"(b1));
}
__device__ __forceinline__ uint32_t movm(uint32_t a) {
    uint32_t d;
    asm volatile("movmatrix.sync.aligned.m8n8.trans.b16 %0,%1;" : "=r"(d) : "r"(a));
    return d;
}
__device__ __forceinline__ uint32_t cvt2(float even, float odd) {
    uint32_t h; asm("cvt.rn.bf16x2.f32 %0,%1,%2;" : "=r"(h) : "f"(odd), "f"(even));
    return h;
}
__device__ __forceinline__ uint32_t lores(uint32_t h, float e, float o) {
    float he = __uint_as_float(h << 16);
    float ho = __uint_as_float(h & 0xffff0000u);
    return cvt2(e - he, o - ho);
}

__device__ __forceinline__ void zeroD(float (&D)[2][4][4]) {
    #pragma unroll
    for (int m = 0; m < 2; m++)
        #pragma unroll
        for (int n = 0; n < 4; n++)
            #pragma unroll
            for (int k = 0; k < 4; k++) D[m][n][k] = 0.0f;
}

// D accum frags -> bf16x2 hi/lo packs. H[Mt][nt][rr] = 8x8 tile(rowtile 2Mt+rr, coltile nt)
__device__ __forceinline__ void packHL(const float (&D)[2][4][4],
                                       uint32_t (&H)[2][4][2], uint32_t (&L)[2][4][2]) {
    #pragma unroll
    for (int Mt = 0; Mt < 2; Mt++)
        #pragma unroll
        for (int nt = 0; nt < 4; nt++)
            #pragma unroll
            for (int rr = 0; rr < 2; rr++) {
                float e = D[Mt][nt][2 * rr], o = D[Mt][nt][2 * rr + 1];
                uint32_t h = cvt2(e, o);
                H[Mt][nt][rr] = h;
                L[Mt][nt][rr] = lores(h, e, o);
            }
}

// ---- gramreg: D += M^T M where MT tiles (A-layout frags of M^T) given as T4[i][k] ----
__device__ __forceinline__ void gramreg(const uint32_t (&TH4)[4][4],
                                        const uint32_t (&TL4)[4][4],
                                        float (&D)[2][4][4]) {
    #pragma unroll
    for (int Kt = 0; Kt < 2; Kt++)
        #pragma unroll
        for (int Mt = 0; Mt < 2; Mt++) {
            uint32_t aH[4] = {TH4[2*Mt][2*Kt],   TH4[2*Mt+1][2*Kt],
                              TH4[2*Mt][2*Kt+1], TH4[2*Mt+1][2*Kt+1]};
            uint32_t aL[4] = {TL4[2*Mt][2*Kt],   TL4[2*Mt+1][2*Kt],
                              TL4[2*Mt][2*Kt+1], TL4[2*Mt+1][2*Kt+1]};
            #pragma unroll
            for (int nt = 0; nt < 4; nt++) {
                uint32_t b0h = TH4[nt][2*Kt], b1h = TH4[nt][2*Kt+1];
                uint32_t b0l = TL4[nt][2*Kt], b1l = TL4[nt][2*Kt+1];
                mmabf(D[Mt][nt], aH, b0h, b1h);
                mmabf(D[Mt][nt], aH, b0l, b1l);
                mmabf(D[Mt][nt], aL, b0h, b1h);
            }
        }
}

// ---- mulXT: D += X * T. X tiles XH/XL[i][k] (row-major A-layout); T sym packs ----
__device__ __forceinline__ void mulXT(const uint32_t (&XH)[4][4], const uint32_t (&XL)[4][4],
                                      const uint32_t (&TH)[2][4][2], const uint32_t (&TL)[2][4][2],
                                      float (&D)[2][4][4]) {
    #pragma unroll
    for (int Kt = 0; Kt < 2; Kt++)
        #pragma unroll
        for (int Mt = 0; Mt < 2; Mt++) {
            uint32_t aH[4] = {XH[2*Mt][2*Kt],   XH[2*Mt+1][2*Kt],
                              XH[2*Mt][2*Kt+1], XH[2*Mt+1][2*Kt+1]};
            uint32_t aL[4] = {XL[2*Mt][2*Kt],   XL[2*Mt+1][2*Kt],
                              XL[2*Mt][2*Kt+1], XL[2*Mt+1][2*Kt+1]};
            #pragma unroll
            for (int nt = 0; nt < 4; nt++) {
                uint32_t b0h = TH[nt >> 1][2*Kt][nt & 1];
                uint32_t b1h = TH[nt >> 1][2*Kt+1][nt & 1];
                uint32_t b0l = TL[nt >> 1][2*Kt][nt & 1];
                uint32_t b1l = TL[nt >> 1][2*Kt+1][nt & 1];
                mmabf(D[Mt][nt], aH, b0h, b1h);
                mmabf(D[Mt][nt], aH, b0l, b1l);
                mmabf(D[Mt][nt], aL, b0h, b1h);
            }
        }
}

// ---- sqsym: D += G * G, G symmetric, from packs ----
__device__ __forceinline__ void sqsym(const uint32_t (&GH)[2][4][2],
                                      const uint32_t (&GL)[2][4][2],
                                      float (&D)[2][4][4]) {
    #pragma unroll
    for (int Kt = 0; Kt < 2; Kt++)
        #pragma unroll
        for (int Mt = 0; Mt < 2; Mt++) {
            uint32_t aH[4] = {GH[Mt][2*Kt][0], GH[Mt][2*Kt][1],
                              GH[Mt][2*Kt+1][0], GH[Mt][2*Kt+1][1]};
            uint32_t aL[4] = {GL[Mt][2*Kt][0], GL[Mt][2*Kt][1],
                              GL[Mt][2*Kt+1][0], GL[Mt][2*Kt+1][1]};
            #pragma unroll
            for (int nt = 0; nt < 4; nt++) {
                uint32_t b0h = GH[nt >> 1][2*Kt][nt & 1];
                uint32_t b1h = GH[nt >> 1][2*Kt+1][nt & 1];
                uint32_t b0l = GL[nt >> 1][2*Kt][nt & 1];
                uint32_t b1l = GL[nt >> 1][2*Kt+1][nt & 1];
                mmabf(D[Mt][nt], aH, b0h, b1h);
                mmabf(D[Mt][nt], aH, b0l, b1l);
                mmabf(D[Mt][nt], aL, b0h, b1h);
            }
        }
}

__global__ __launch_bounds__(32) void fiber_bundle_kernel(
    const int*   __restrict__ tokens,
    const float* __restrict__ base_w,
    const float* __restrict__ fiber_w,
    const float* __restrict__ conn_w,
    const float* __restrict__ gen,
    float*       __restrict__ out)
{
    const int lane = threadIdx.x;
    const int rw = lane >> 2;              // frag row within 8 (A-layout)
    const int cp = (lane & 3) * 2;         // frag col pair base

    const int tokIdx = blockIdx.x;
    const int tok    = tokens[tokIdx];

    // ---- side-copy loads issued early ----
    float4 breg[4];
    {
        const float4* bsrc = (const float4*)(base_w + (size_t)tok * 512);
        #pragma unroll
        for (int j = 0; j < 4; j++) breg[j] = bsrc[lane + 32 * j];
    }
    float cv = 0.0f;
    if (lane < 8) cv = conn_w[(size_t)tok * 8 + lane];
    float4 gv;
    const bool doGen = blockIdx.x < 64;
    if (doGen) gv = ((const float4*)gen)[blockIdx.x * 32 + lane];

    // ---- load X directly in fragment layout (16 LDG.64), split hi/lo ----
    uint32_t XH[4][4], XL[4][4];           // X tiles [rowtile][coltile]
    {
        const float* fx = fiber_w + (size_t)tok * 1024;
        #pragma unroll
        for (int i = 0; i < 4; i++)
            #pragma unroll
            for (int j = 0; j < 4; j++) {
                float2 v = *(const float2*)(fx + (8 * i + rw) * 32 + 8 * j + cp);
                uint32_t h = cvt2(v.x, v.y);
                XH[i][j] = h;
                XL[i][j] = lores(h, v.x, v.y);
            }
    }

    // ---- retire side copies ----
    {
        float4* bdst = (float4*)(out + (size_t)tokIdx * 512);
        #pragma unroll
        for (int j = 0; j < 4; j++) bdst[lane + 32 * j] = breg[j];
    }
    if (lane < 8) out[OUT_CONN + (size_t)tokIdx * 8 + lane] = cv;
    if (doGen) ((float4*)(out + OUT_GEN))[blockIdx.x * 32 + lane] = gv;

    // ---- X^T tiles via movmatrix ----
    uint32_t MH[4][4], ML[4][4];           // X^T tiles [rowtile][coltile]
    #pragma unroll
    for (int i = 0; i < 4; i++)
        #pragma unroll
        for (int j = 0; j < 4; j++) {
            MH[i][j] = movm(XH[j][i]);
            ML[i][j] = movm(XL[j][i]);
        }

    float D[2][4][4];
    uint32_t H[2][4][2], L[2][4][2];

    // ===== (1) G = X^T X  (all regs) =====
    zeroD(D);
    gramreg(MH, ML, D);

    // ===== (2) T = 0.375*(G*G + 5I - (10/3)G)  (all regs) =====
    packHL(D, H, L);                       // G packs
    #pragma unroll
    for (int Mt = 0; Mt < 2; Mt++)
        #pragma unroll
        for (int nt = 0; nt < 4; nt++) {
            const int c0 = nt * 8 + cp;
            const int r0 = Mt * 16 + rw, r1 = r0 + 8;
            D[Mt][nt][0] = fmaf(D[Mt][nt][0], -3.33333333f, (r0 == c0)     ? 5.0f : 0.0f);
            D[Mt][nt][1] = fmaf(D[Mt][nt][1], -3.33333333f, (r0 == c0 + 1) ? 5.0f : 0.0f);
            D[Mt][nt][2] = fmaf(D[Mt][nt][2], -3.33333333f, (r1 == c0)     ? 5.0f : 0.0f);
            D[Mt][nt][3] = fmaf(D[Mt][nt][3], -3.33333333f, (r1 == c0 + 1) ? 5.0f : 0.0f);
        }
    sqsym(H, L, D);
    #pragma unroll
    for (int Mt = 0; Mt < 2; Mt++)
        #pragma unroll
        for (int nt = 0; nt < 4; nt++)
            #pragma unroll
            for (int k = 0; k < 4; k++) D[Mt][nt][k] *= 0.375f;
    packHL(D, H, L);                       // T packs

    // ===== (3) X1 = X * T  (all regs) =====
    zeroD(D);
    mulXT(XH, XL, H, L, D);

    // ===== (4) G2 = X1^T X1  (all regs via movmatrix) =====
    packHL(D, H, L);                       // X1 packs; X1 tile(i,j) = H[i>>1][j][i&1]
    #pragma unroll
    for (int i = 0; i < 4; i++)
        #pragma unroll
        for (int j = 0; j < 4; j++) {      // X1^T tiles (reuse MH/ML)
            MH[i][j] = movm(H[j >> 1][i][j & 1]);
            ML[i][j] = movm(L[j >> 1][i][j & 1]);
        }
    zeroD(D);
    gramreg(MH, ML, D);                    // D = G2

    // E = 0.5*(I - G2)  -> single bf16 plane in regs
    uint32_t EH[2][4][2];
    #pragma unroll
    for (int Mt = 0; Mt < 2; Mt++)
        #pragma unroll
        for (int nt = 0; nt < 4; nt++) {
            const int c0 = nt * 8 + cp;
            const int r0 = Mt * 16 + rw, r1 = r0 + 8;
            float e0 = 0.5f * (((r0 == c0)     ? 1.0f : 0.0f) - D[Mt][nt][0]);
            float e1 = 0.5f * (((r0 == c0 + 1) ? 1.0f : 0.0f) - D[Mt][nt][1]);
            float e2 = 0.5f * (((r1 == c0)     ? 1.0f : 0.0f) - D[Mt][nt][2]);
            float e3 = 0.5f * (((r1 == c0 + 1) ? 1.0f : 0.0f) - D[Mt][nt][3]);
            EH[Mt][nt][0] = cvt2(e0, e1);
            EH[Mt][nt][1] = cvt2(e2, e3);
        }

    // ===== (5) Xf = X1 + X1h * E  (accumulator initialized from X1 packs) =====
    #pragma unroll
    for (int Mt = 0; Mt < 2; Mt++)
        #pragma unroll
        for (int nt = 0; nt < 4; nt++)
            #pragma unroll
            for (int rr = 0; rr < 2; rr++) {
                uint32_t h = H[Mt][nt][rr], l = L[Mt][nt][rr];
                D[Mt][nt][2 * rr]     = __uint_as_float(h << 16)
                                      + __uint_as_float(l << 16);
                D[Mt][nt][2 * rr + 1] = __uint_as_float(h & 0xffff0000u)
                                      + __uint_as_float(l & 0xffff0000u);
            }
    #pragma unroll
    for (int Kt = 0; Kt < 2; Kt++)
        #pragma unroll
        for (int Mt = 0; Mt < 2; Mt++) {
            uint32_t aH[4] = {H[Mt][2*Kt][0], H[Mt][2*Kt][1],
                              H[Mt][2*Kt+1][0], H[Mt][2*Kt+1][1]};
            #pragma unroll
            for (int nt = 0; nt < 4; nt++)
                mmabf(D[Mt][nt], aH,
                      EH[nt >> 1][2*Kt][nt & 1],
                      EH[nt >> 1][2*Kt+1][nt & 1]);
        }

    // ---- write fiber output ----
    {
        float* fdst = out + OUT_FIBER + (size_t)tokIdx * 1024;
        #pragma unroll
        for (int Mt = 0; Mt < 2; Mt++)
            #pragma unroll
            for (int nt = 0; nt < 4; nt++) {
                const int c0 = nt * 8 + cp;
                const int r0 = Mt * 16 + rw;
                *(float2*)(fdst + r0 * 32 + c0)       = make_float2(D[Mt][nt][0], D[Mt][nt][1]);
                *(float2*)(fdst + (r0 + 8) * 32 + c0) = make_float2(D[Mt][nt][2], D[Mt][nt][3]);
            }
    }
}

extern "C" void kernel_launch(void* const* d_in, const int* in_sizes, int n_in,
                              void* d_out, int out_size)
{
    const int*   tokens  = (const int*)  d_in[0];
    const float* base_w  = (const float*)d_in[1];
    const float* fiber_w = (const float*)d_in[2];
    const float* conn_w  = (const float*)d_in[3];
    const float* gen     = (const float*)d_in[4];
    float* out = (float*)d_out;

    dim3 grid(NTOK);       // 32768 one-warp blocks, 1 matrix each
    dim3 block(32);
    fiber_bundle_kernel<<<grid, block>>>(tokens, base_w, fiber_w, conn_w, gen, out);
}